// round 2
// baseline (speedup 1.0000x reference)
#include <cuda_runtime.h>
#include <math.h>

#define BB 32
#define NN 577
#define DD 384
#define LL 12
#define NRPT 4
#define HH 1536
#define MMAX 580   // NN + NRPT - 1

// ---------------- scratch (static device arrays; no allocation) ----------------
__device__ float g_x[BB * NN * DD];
__device__ float g_xn[BB * NN * DD];
__device__ float g_q[BB * NN * DD];
__device__ float g_prod[BB * NN * DD];
__device__ float g_mem[BB * MMAX * DD];
__device__ float g_k[BB * MMAX * DD];
__device__ float g_v[BB * MMAX * DD];
__device__ float g_scores[BB * NN * MMAX];
__device__ float g_h[BB * NN * HH];
__device__ float g_hist[NRPT * BB * DD];

// ---------------- elementwise helpers ----------------
__global__ void copy_kernel(float* __restrict__ dst, const float* __restrict__ src, int n) {
    int i = blockIdx.x * 256 + threadIdx.x;
    if (i < n) dst[i] = src[i];
}

__global__ void save_cls_kernel(const float* __restrict__ x, float* __restrict__ hist_r) {
    int i = blockIdx.x * 256 + threadIdx.x;
    if (i >= BB * DD) return;
    int b = i / DD, d = i % DD;
    hist_r[i] = x[(size_t)b * NN * DD + d];
}

__global__ void restore_patches_kernel(float* __restrict__ x, const float* __restrict__ x_in) {
    int i = blockIdx.x * 256 + threadIdx.x;
    if (i >= BB * NN * DD) return;
    int tok = (i / DD) % NN;
    if (tok != 0) x[i] = x_in[i];
}

__global__ void build_mem_kernel(float* __restrict__ mem, const float* __restrict__ x,
                                 const float* __restrict__ hist, int Mk) {
    int i = blockIdx.x * 256 + threadIdx.x;
    if (i >= BB * Mk * DD) return;
    int d = i % DD;
    int t = (i / DD) % Mk;
    int b = i / (DD * Mk);
    float v;
    if (t < NN) v = x[((size_t)b * NN + t) * DD + d];
    else        v = hist[((size_t)(t - NN) * BB + b) * DD + d];
    mem[i] = v;
}

// ---------------- layernorm: 1 warp per row, D=384 = 12 per lane ----------------
__global__ void ln_kernel(const float* __restrict__ in, float* __restrict__ out,
                          const float* __restrict__ w, const float* __restrict__ b, int rows) {
    int row = blockIdx.x * 8 + (threadIdx.x >> 5);
    int lane = threadIdx.x & 31;
    if (row >= rows) return;
    const float* p = in + (size_t)row * DD;
    float v[12];
    float s = 0.f;
#pragma unroll
    for (int i = 0; i < 12; i++) { v[i] = p[lane + 32 * i]; s += v[i]; }
#pragma unroll
    for (int o = 16; o; o >>= 1) s += __shfl_xor_sync(0xffffffffu, s, o);
    float mu = s * (1.0f / DD);
    float var = 0.f;
#pragma unroll
    for (int i = 0; i < 12; i++) { float dd = v[i] - mu; var += dd * dd; }
#pragma unroll
    for (int o = 16; o; o >>= 1) var += __shfl_xor_sync(0xffffffffu, var, o);
    float inv = rsqrtf(var * (1.0f / DD) + 1e-6f);
    float* q = out + (size_t)row * DD;
#pragma unroll
    for (int i = 0; i < 12; i++) {
        int c = lane + 32 * i;
        q[c] = (v[i] - mu) * inv * w[c] + b[c];
    }
}

// ---------------- softmax: 1 warp per row, len Mk <= 580, row stride MMAX ----------------
__global__ void softmax_kernel(float* __restrict__ s, int rows, int Mk) {
    int row = blockIdx.x * 8 + (threadIdx.x >> 5);
    int lane = threadIdx.x & 31;
    if (row >= rows) return;
    float* p = s + (size_t)row * MMAX;
    float v[19];
    float mx = -1e30f;
#pragma unroll
    for (int i = 0; i < 19; i++) {
        int j = lane + 32 * i;
        v[i] = (j < Mk) ? p[j] : -1e30f;
        mx = fmaxf(mx, v[i]);
    }
#pragma unroll
    for (int o = 16; o; o >>= 1) mx = fmaxf(mx, __shfl_xor_sync(0xffffffffu, mx, o));
    float sum = 0.f;
#pragma unroll
    for (int i = 0; i < 19; i++) { v[i] = __expf(v[i] - mx); sum += v[i]; }
#pragma unroll
    for (int o = 16; o; o >>= 1) sum += __shfl_xor_sync(0xffffffffu, sum, o);
    float r = 1.0f / sum;
#pragma unroll
    for (int i = 0; i < 19; i++) {
        int j = lane + 32 * i;
        if (j < Mk) p[j] = v[i] * r;
    }
}

__device__ __forceinline__ float gelu_exact(float v) {
    return 0.5f * v * (1.0f + erff(v * 0.70710678118654752f));
}

#define FMA16()                                                                              \
    acc[0][0] += a4.x * b4.x; acc[0][1] += a4.x * b4.y; acc[0][2] += a4.x * b4.z; acc[0][3] += a4.x * b4.w; \
    acc[1][0] += a4.y * b4.x; acc[1][1] += a4.y * b4.y; acc[1][2] += a4.y * b4.z; acc[1][3] += a4.y * b4.w; \
    acc[2][0] += a4.z * b4.x; acc[2][1] += a4.z * b4.y; acc[2][2] += a4.z * b4.z; acc[2][3] += a4.z * b4.w; \
    acc[3][0] += a4.w * b4.x; acc[3][1] += a4.w * b4.y; acc[3][2] += a4.w * b4.z; acc[3][3] += a4.w * b4.w;

// ---------------- C = A * W^T (+epilogue). A:[M,K] ldK, W:[Nc,K] ldK, C:[M,ldc] ----------
// epi 0: C = acc*alpha + bias        (bias may be null)
// epi 1: C = gelu(acc + bias)
// epi 2: C = (acc + bias)*ls + res
// K must be a multiple of 16 (all NT uses: K in {384, 1536}).
__global__ void gemm_nt_kernel(const float* __restrict__ A, const float* __restrict__ W,
                               const float* __restrict__ bias, const float* __restrict__ ls,
                               const float* __restrict__ res, float* __restrict__ C,
                               int Mrows, int Ncols, int K, int ldc,
                               long sA, long sW, long sC, float alpha, int epi) {
    __shared__ __align__(16) float As[16][64];
    __shared__ __align__(16) float Bs[16][64];
    int bz = blockIdx.z;
    A += (size_t)bz * sA;
    W += (size_t)bz * sW;
    C += (size_t)bz * sC;
    const float* resp = res ? res + (size_t)bz * sC : (const float*)0;
    int m0 = blockIdx.y * 64, n0 = blockIdx.x * 64;
    int tid = threadIdx.x;
    int tx = tid & 15, ty = tid >> 4;
    int lr = tid >> 2, lk = (tid & 3) << 2;
    float acc[4][4] = {};
    int gmL = m0 + lr;
    int gnL = n0 + lr;
    const float* Aptr = A + (size_t)gmL * K + lk;
    const float* Wptr = W + (size_t)gnL * K + lk;
    bool am = gmL < Mrows, wn = gnL < Ncols;
    for (int k0 = 0; k0 < K; k0 += 16) {
        float4 av = am ? *(const float4*)(Aptr + k0) : make_float4(0, 0, 0, 0);
        float4 wv = wn ? *(const float4*)(Wptr + k0) : make_float4(0, 0, 0, 0);
        As[lk + 0][lr] = av.x; As[lk + 1][lr] = av.y; As[lk + 2][lr] = av.z; As[lk + 3][lr] = av.w;
        Bs[lk + 0][lr] = wv.x; Bs[lk + 1][lr] = wv.y; Bs[lk + 2][lr] = wv.z; Bs[lk + 3][lr] = wv.w;
        __syncthreads();
#pragma unroll
        for (int k = 0; k < 16; k++) {
            float4 a4 = *(const float4*)(&As[k][ty << 2]);
            float4 b4 = *(const float4*)(&Bs[k][tx << 2]);
            FMA16();
        }
        __syncthreads();
    }
#pragma unroll
    for (int i = 0; i < 4; i++) {
        int gm = m0 + (ty << 2) + i;
        if (gm >= Mrows) continue;
#pragma unroll
        for (int j = 0; j < 4; j++) {
            int gn = n0 + (tx << 2) + j;
            if (gn >= Ncols) continue;
            float v = acc[i][j] * alpha;
            if (bias) v += bias[gn];
            if (epi == 1) v = gelu_exact(v);
            else if (epi == 2) v = v * ls[gn] + resp[(size_t)gm * ldc + gn];
            C[(size_t)gm * ldc + gn] = v;
        }
    }
}

// ---------------- C = A * B. A:[M,K] lda, B:[K,Nc] ldb (row-major), C:[M,ldc]. ----------
// K-guarded (used for prod = attn @ v where K = Mk is 577..580).
__global__ void gemm_nn_kernel(const float* __restrict__ A, const float* __restrict__ Bm,
                               float* __restrict__ C, int Mrows, int Ncols, int K,
                               int lda, int ldb, int ldc, long sA, long sB, long sC) {
    __shared__ __align__(16) float As[16][64];
    __shared__ __align__(16) float Bs[16][64];
    int bz = blockIdx.z;
    A += (size_t)bz * sA;
    Bm += (size_t)bz * sB;
    C += (size_t)bz * sC;
    int m0 = blockIdx.y * 64, n0 = blockIdx.x * 64;
    int tid = threadIdx.x;
    int tx = tid & 15, ty = tid >> 4;
    int lr = tid >> 2, lk = (tid & 3) << 2;   // A loader
    int bk = tid >> 4, bn = (tid & 15) << 2;  // B loader
    float acc[4][4] = {};
    int gmL = m0 + lr;
    bool am = gmL < Mrows;
    for (int k0 = 0; k0 < K; k0 += 16) {
        float4 av = make_float4(0, 0, 0, 0);
        if (am) {
            int kk = k0 + lk;
            const float* ap = A + (size_t)gmL * lda;
            if (kk + 3 < K) av = *(const float4*)(ap + kk);
            else {
                if (kk < K)     av.x = ap[kk];
                if (kk + 1 < K) av.y = ap[kk + 1];
                if (kk + 2 < K) av.z = ap[kk + 2];
                if (kk + 3 < K) av.w = ap[kk + 3];
            }
        }
        As[lk + 0][lr] = av.x; As[lk + 1][lr] = av.y; As[lk + 2][lr] = av.z; As[lk + 3][lr] = av.w;
        int kb = k0 + bk;
        float4 bv = make_float4(0, 0, 0, 0);
        if (kb < K) bv = *(const float4*)(Bm + (size_t)kb * ldb + n0 + bn);
        *(float4*)(&Bs[bk][bn]) = bv;
        __syncthreads();
#pragma unroll
        for (int k = 0; k < 16; k++) {
            float4 a4 = *(const float4*)(&As[k][ty << 2]);
            float4 b4 = *(const float4*)(&Bs[k][tx << 2]);
            FMA16();
        }
        __syncthreads();
    }
#pragma unroll
    for (int i = 0; i < 4; i++) {
        int gm = m0 + (ty << 2) + i;
        if (gm >= Mrows) continue;
#pragma unroll
        for (int j = 0; j < 4; j++) {
            int gn = n0 + (tx << 2) + j;
            if (gn >= Ncols) continue;
            C[(size_t)gm * ldc + gn] = acc[i][j];
        }
    }
}

// ---------------- host orchestration ----------------
extern "C" void kernel_launch(void* const* d_in, const int* in_sizes, int n_in,
                              void* d_out, int out_size) {
    const float* x_in    = (const float*)d_in[0];
    const float* norm1_w = (const float*)d_in[1];
    const float* norm1_b = (const float*)d_in[2];
    const float* qkv_w   = (const float*)d_in[3];
    const float* qkv_b   = (const float*)d_in[4];
    const float* qn_w    = (const float*)d_in[5];
    const float* qn_b    = (const float*)d_in[6];
    const float* kn_w    = (const float*)d_in[7];
    const float* kn_b    = (const float*)d_in[8];
    const float* an_w    = (const float*)d_in[9];
    const float* an_b    = (const float*)d_in[10];
    const float* proj_w  = (const float*)d_in[11];
    const float* proj_b  = (const float*)d_in[12];
    const float* ls1     = (const float*)d_in[13];
    const float* norm2_w = (const float*)d_in[14];
    const float* norm2_b = (const float*)d_in[15];
    const float* fc1_w   = (const float*)d_in[16];
    const float* fc1_b   = (const float*)d_in[17];
    const float* fc2_w   = (const float*)d_in[18];
    const float* fc2_b   = (const float*)d_in[19];
    const float* ls2     = (const float*)d_in[20];
    float* out = (float*)d_out;

    float *px, *pxn, *pq, *pprod, *pmem, *pk, *pv, *pscores, *ph, *phist;
    cudaGetSymbolAddress((void**)&px, g_x);
    cudaGetSymbolAddress((void**)&pxn, g_xn);
    cudaGetSymbolAddress((void**)&pq, g_q);
    cudaGetSymbolAddress((void**)&pprod, g_prod);
    cudaGetSymbolAddress((void**)&pmem, g_mem);
    cudaGetSymbolAddress((void**)&pk, g_k);
    cudaGetSymbolAddress((void**)&pv, g_v);
    cudaGetSymbolAddress((void**)&pscores, g_scores);
    cudaGetSymbolAddress((void**)&ph, g_h);
    cudaGetSymbolAddress((void**)&phist, g_hist);

    const float scale = 1.0f / sqrtf((float)DD);
    const int nXND = BB * NN * DD;

    copy_kernel<<<(nXND + 255) / 256, 256>>>(px, x_in, nXND);

    for (int r = 0; r < NRPT; r++) {
        int Mk = NN + r;
        int rowsX = BB * NN;
        int rowsM = BB * Mk;

        save_cls_kernel<<<(BB * DD + 255) / 256, 256>>>(px, phist + (size_t)r * BB * DD);
        restore_patches_kernel<<<(nXND + 255) / 256, 256>>>(px, x_in);
        build_mem_kernel<<<(BB * Mk * DD + 255) / 256, 256>>>(pmem, px, phist, Mk);

        for (int l = 0; l < LL; l++) {
            const float* Wq = qkv_w + (size_t)l * 3 * DD * DD;
            const float* Wk = Wq + (size_t)DD * DD;
            const float* Wv = Wq + (size_t)2 * DD * DD;
            const float* bq = qkv_b + (size_t)l * 3 * DD;
            const float* bk_ = bq + DD;
            const float* bv_ = bq + 2 * DD;

            // norm1
            ln_kernel<<<(rowsX + 7) / 8, 256>>>(px, pxn, norm1_w + l * DD, norm1_b + l * DD, rowsX);

            // q = ln(x) @ Wq^T + bq ; k,v from mem (no pre-norm)
            dim3 g1(DD / 64, (rowsX + 63) / 64, 1);
            gemm_nt_kernel<<<g1, 256>>>(pxn, Wq, bq, 0, 0, pq, rowsX, DD, DD, DD, 0, 0, 0, 1.0f, 0);
            dim3 g2(DD / 64, (rowsM + 63) / 64, 1);
            gemm_nt_kernel<<<g2, 256>>>(pmem, Wk, bk_, 0, 0, pk, rowsM, DD, DD, DD, 0, 0, 0, 1.0f, 0);
            gemm_nt_kernel<<<g2, 256>>>(pmem, Wv, bv_, 0, 0, pv, rowsM, DD, DD, DD, 0, 0, 0, 1.0f, 0);

            // q/k layernorms (in place)
            ln_kernel<<<(rowsX + 7) / 8, 256>>>(pq, pq, qn_w + l * DD, qn_b + l * DD, rowsX);
            ln_kernel<<<(rowsM + 7) / 8, 256>>>(pk, pk, kn_w + l * DD, kn_b + l * DD, rowsM);

            // scores = scale * q @ k^T (batched over B), then softmax
            dim3 gs((Mk + 63) / 64, (NN + 63) / 64, BB);
            gemm_nt_kernel<<<gs, 256>>>(pq, pk, 0, 0, 0, pscores, NN, Mk, DD, MMAX,
                                        (long)NN * DD, (long)Mk * DD, (long)NN * MMAX, scale, 0);
            softmax_kernel<<<(BB * NN + 7) / 8, 256>>>(pscores, BB * NN, Mk);

            // prod = attn @ v (batched)
            dim3 gp(DD / 64, (NN + 63) / 64, BB);
            gemm_nn_kernel<<<gp, 256>>>(pscores, pv, pprod, NN, DD, Mk, MMAX, DD, DD,
                                        (long)NN * MMAX, (long)Mk * DD, (long)NN * DD);

            // attn-out layernorm, then proj with ls1*acc + residual epilogue (in-place on x)
            ln_kernel<<<(rowsX + 7) / 8, 256>>>(pprod, pprod, an_w + l * DD, an_b + l * DD, rowsX);
            gemm_nt_kernel<<<g1, 256>>>(pprod, proj_w + (size_t)l * DD * DD, proj_b + l * DD,
                                        ls1 + l * DD, px, px, rowsX, DD, DD, DD, 0, 0, 0, 1.0f, 2);

            // MLP: norm2 -> fc1(+gelu) -> fc2(+ls2*acc + residual)
            ln_kernel<<<(rowsX + 7) / 8, 256>>>(px, pxn, norm2_w + l * DD, norm2_b + l * DD, rowsX);
            dim3 gh(HH / 64, (rowsX + 63) / 64, 1);
            gemm_nt_kernel<<<gh, 256>>>(pxn, fc1_w + (size_t)l * HH * DD, fc1_b + l * HH,
                                        0, 0, ph, rowsX, HH, DD, HH, 0, 0, 0, 1.0f, 1);
            gemm_nt_kernel<<<g1, 256>>>(ph, fc2_w + (size_t)l * DD * HH, fc2_b + l * DD,
                                        ls2 + l * DD, px, px, rowsX, DD, HH, DD, 0, 0, 0, 1.0f, 2);
        }
    }

    copy_kernel<<<(nXND + 255) / 256, 256>>>(out, px, nXND);
}

// round 5
// speedup vs baseline: 2.9616x; 2.9616x over previous
#include <cuda_runtime.h>
#include <cuda_bf16.h>
#include <math.h>
#include <stdint.h>

#define BB 32
#define NN 577
#define DD 384
#define LL 12
#define NRPT 4
#define HH 1536
#define MMAX 580
#define MPAD 640

// ---------------- scratch (static device arrays; no allocation) ----------------
__device__ float g_x[BB * NN * DD];
__device__ float g_q[BB * NN * DD];      // q GEMM out; reused for prod out
__device__ float g_k[BB * MMAX * DD];
__device__ float g_scores[(size_t)BB * NN * MPAD];
__device__ float g_hist[NRPT * BB * DD];
__device__ __nv_bfloat16 g_mem_bf[BB * MMAX * DD];
__device__ __nv_bfloat16 g_xn_bf[BB * NN * DD];
__device__ __nv_bfloat16 g_qbf[BB * NN * DD];
__device__ __nv_bfloat16 g_kbf[BB * MMAX * DD];
__device__ __nv_bfloat16 g_vT[BB * DD * MPAD];
__device__ __nv_bfloat16 g_attn[(size_t)BB * NN * MPAD];
__device__ __nv_bfloat16 g_pn[BB * NN * DD];
__device__ __nv_bfloat16 g_h[(size_t)BB * NN * HH];
__device__ __nv_bfloat16 g_wqkv[LL * 3 * DD * DD];
__device__ __nv_bfloat16 g_wproj[LL * DD * DD];
__device__ __nv_bfloat16 g_wfc1[LL * HH * DD];
__device__ __nv_bfloat16 g_wfc2[LL * DD * HH];

// ---------------- PTX helpers (compute_103-safe: no tcgen05, no mbarrier needed) --------
__device__ __forceinline__ uint32_t smem_u32(const void* p) {
    uint32_t a;
    asm("{ .reg .u64 t; cvta.to.shared.u64 t, %1; cvt.u32.u64 %0, t; }" : "=r"(a) : "l"(p));
    return a;
}
__device__ __forceinline__ void cpasync16(uint32_t dst, const void* src, int srcsize) {
    asm volatile("cp.async.ca.shared.global [%0], [%1], 16, %2;" :: "r"(dst), "l"(src), "r"(srcsize));
}
__device__ __forceinline__ void cpcommit() { asm volatile("cp.async.commit_group;" ::: "memory"); }
__device__ __forceinline__ void cpwait1() { asm volatile("cp.async.wait_group 1;" ::: "memory"); }
__device__ __forceinline__ void cpwait0() { asm volatile("cp.async.wait_group 0;" ::: "memory"); }

#define LDSM4(r0, r1, r2, r3, a)                                                     \
    asm volatile("ldmatrix.sync.aligned.m8n8.x4.shared.b16 {%0,%1,%2,%3}, [%4];"     \
                 : "=r"(r0), "=r"(r1), "=r"(r2), "=r"(r3) : "r"(a))

#define MMA16816(d, av, bv)                                                          \
    asm volatile("mma.sync.aligned.m16n8k16.row.col.f32.bf16.bf16.f32 "              \
                 "{%0,%1,%2,%3},{%4,%5,%6,%7},{%8,%9},{%0,%1,%2,%3};"                \
                 : "+f"((d)[0]), "+f"((d)[1]), "+f"((d)[2]), "+f"((d)[3])            \
                 : "r"((av)[0]), "r"((av)[1]), "r"((av)[2]), "r"((av)[3]),           \
                   "r"((bv)[0]), "r"((bv)[1]))

// smem layout (relative to 1024-aligned base): A[128][64]bf16, B[128][64]bf16, x2 buffers
#define SM_A(s) ((s) * 32768)
#define SM_B(s) ((s) * 32768 + 16384)
#define SMEM_DYN (65536 + 1024)

__device__ __forceinline__ float gelu_exact(float v) {
    return 0.5f * v * (1.0f + erff(v * 0.70710678118654752f));
}

__device__ __forceinline__ void st_epi(int mode, void* Cv, long zC, int bz, int ldc,
                                       const float* bias, const float* ls, const float* resp,
                                       int gm, int gn, int Mrows, int Nvalid, int Npad,
                                       float alpha, float acc) {
    if (gm >= Mrows) return;
    if (mode == 3) {
        if (gn >= Npad) return;
        __nv_bfloat16* C = (__nv_bfloat16*)Cv + (size_t)bz * zC;
        float v = 0.f;
        if (gn < Nvalid) v = acc + (bias ? bias[gm] : 0.f);
        C[(size_t)gm * ldc + gn] = __float2bfloat16(v);
        return;
    }
    if (gn >= Nvalid) return;
    if (mode == 0) {
        float* C = (float*)Cv + (size_t)bz * zC;
        float v = acc * alpha;
        if (bias) v += bias[gn];
        C[(size_t)gm * ldc + gn] = v;
    } else if (mode == 1) {
        __nv_bfloat16* C = (__nv_bfloat16*)Cv + (size_t)bz * zC;
        C[(size_t)gm * ldc + gn] = __float2bfloat16(gelu_exact(acc + bias[gn]));
    } else {
        float* C = (float*)Cv + (size_t)bz * zC;
        C[(size_t)gm * ldc + gn] = (acc + bias[gn]) * ls[gn] + resp[(size_t)gm * ldc + gn];
    }
}

// ---------------- HMMA GEMM: C[M,*] = A[M,K](bf16) @ W[N,K]^T(bf16) + epilogue ----------
// Block: 256 threads = 8 warps (4 x 2). Tile 128x128, K-chunk 64, double-buffered cp.async.
// mode 0: f32 out, v = acc*alpha + bias[gn]
// mode 1: bf16 out, v = gelu(acc + bias[gn])
// mode 2: f32 out, v = (acc + bias[gn])*ls[gn] + res[gm*ldc+gn]
// mode 3: bf16 out, v = acc + bias[gm]; zero-fill cols [Nvalid, Npad)
__global__ void __launch_bounds__(256)
mma_gemm_nt(const __nv_bfloat16* __restrict__ A, const __nv_bfloat16* __restrict__ W,
            const float* __restrict__ bias, const float* __restrict__ ls,
            const float* __restrict__ res, void* __restrict__ Cv,
            int Mrows, int Nvalid, int Npad, int K, int lda, int ldw, int ldc,
            long zA, long zW, long zC, float alpha, int mode) {
    extern __shared__ char smraw[];
    uint32_t sbase = (smem_u32(smraw) + 1023u) & ~1023u;
    int tid = threadIdx.x, wid = tid >> 5, lid = tid & 31;
    int bz = blockIdx.z;
    A += (size_t)bz * zA;
    W += (size_t)bz * zW;
    const float* resp = res ? res + (size_t)bz * zC : (const float*)0;
    int m0 = blockIdx.y * 128, n0 = blockIdx.x * 128;

    int wm = wid & 3;   // row group: wm*32
    int wn = wid >> 2;  // col group: wn*64

    float acc[2][8][4];
#pragma unroll
    for (int a = 0; a < 2; a++)
#pragma unroll
        for (int b = 0; b < 8; b++)
#pragma unroll
            for (int c = 0; c < 4; c++) acc[a][b][c] = 0.f;

    int nk = K >> 6;

    // chunk kc -> buffer s. rows of 64 bf16 = 128B = 8 granules of 16B, XOR-swizzled.
#define LOAD_CHUNK(kc, s) do {                                                         \
    int _k0 = (kc) << 6;                                                               \
    _Pragma("unroll")                                                                  \
    for (int _i = 0; _i < 4; _i++) {                                                   \
        int _idx = tid + 256 * _i;                                                     \
        int _row = _idx >> 3, _g = _idx & 7;                                           \
        int _gm = m0 + _row;                                                           \
        int _pr = (_gm < Mrows) ? 16 : 0;                                              \
        const __nv_bfloat16* _src = A + (size_t)(_pr ? _gm : 0) * lda + _k0 + _g * 8;  \
        cpasync16(sbase + SM_A(s) + _row * 128 + (((_g ^ (_row & 7))) << 4), _src, _pr); \
    }                                                                                  \
    _Pragma("unroll")                                                                  \
    for (int _i = 0; _i < 4; _i++) {                                                   \
        int _idx = tid + 256 * _i;                                                     \
        int _row = _idx >> 3, _g = _idx & 7;                                           \
        int _gn = n0 + _row;                                                           \
        int _pr = (_gn < Nvalid) ? 16 : 0;                                             \
        const __nv_bfloat16* _src = W + (size_t)(_pr ? _gn : 0) * ldw + _k0 + _g * 8;  \
        cpasync16(sbase + SM_B(s) + _row * 128 + (((_g ^ (_row & 7))) << 4), _src, _pr); \
    }                                                                                  \
    cpcommit();                                                                        \
} while (0)

    LOAD_CHUNK(0, 0);
    int grp = lid >> 3, rin = lid & 7;
    for (int i = 0; i < nk; i++) {
        int s = i & 1;
        if (i + 1 < nk) { LOAD_CHUNK(i + 1, s ^ 1); cpwait1(); }
        else cpwait0();
        __syncthreads();
#pragma unroll
        for (int ks = 0; ks < 4; ks++) {
            uint32_t af[2][4], bf[8][2];
            // A fragments: m-tiles at rows wm*32 + {0,16}
#pragma unroll
            for (int mt = 0; mt < 2; mt++) {
                int row = wm * 32 + mt * 16 + rin + (grp & 1) * 8;
                int kg = ks * 2 + (grp >> 1);
                uint32_t ad = sbase + SM_A(s) + row * 128 + ((kg ^ (row & 7)) << 4);
                LDSM4(af[mt][0], af[mt][1], af[mt][2], af[mt][3], ad);
            }
            // B fragments: n-tile pairs at rows wn*64 + np*16
#pragma unroll
            for (int np = 0; np < 4; np++) {
                int row = wn * 64 + np * 16 + rin + (grp >> 1) * 8;
                int kg = ks * 2 + (grp & 1);
                uint32_t ad = sbase + SM_B(s) + row * 128 + ((kg ^ (row & 7)) << 4);
                LDSM4(bf[2 * np][0], bf[2 * np][1], bf[2 * np + 1][0], bf[2 * np + 1][1], ad);
            }
#pragma unroll
            for (int mt = 0; mt < 2; mt++)
#pragma unroll
                for (int nt = 0; nt < 8; nt++)
                    MMA16816(acc[mt][nt], af[mt], bf[nt]);
        }
        __syncthreads();
    }

    // epilogue: lane l of mma tile: rows (l>>2), (l>>2)+8; cols (l&3)*2, +1
#pragma unroll
    for (int mt = 0; mt < 2; mt++) {
        int r0 = m0 + wm * 32 + mt * 16 + (lid >> 2);
#pragma unroll
        for (int nt = 0; nt < 8; nt++) {
            int c0 = n0 + wn * 64 + nt * 8 + (lid & 3) * 2;
            st_epi(mode, Cv, zC, bz, ldc, bias, ls, resp, r0,     c0,     Mrows, Nvalid, Npad, alpha, acc[mt][nt][0]);
            st_epi(mode, Cv, zC, bz, ldc, bias, ls, resp, r0,     c0 + 1, Mrows, Nvalid, Npad, alpha, acc[mt][nt][1]);
            st_epi(mode, Cv, zC, bz, ldc, bias, ls, resp, r0 + 8, c0,     Mrows, Nvalid, Npad, alpha, acc[mt][nt][2]);
            st_epi(mode, Cv, zC, bz, ldc, bias, ls, resp, r0 + 8, c0 + 1, Mrows, Nvalid, Npad, alpha, acc[mt][nt][3]);
        }
    }
}

// ---------------- small kernels ----------------
__global__ void copy_kernel(float* __restrict__ dst, const float* __restrict__ src, int n) {
    int i = blockIdx.x * 256 + threadIdx.x;
    if (i < n) dst[i] = src[i];
}
__global__ void cvt_bf_kernel(__nv_bfloat16* __restrict__ dst, const float* __restrict__ src, int n) {
    int i = blockIdx.x * 256 + threadIdx.x;
    if (i < n) dst[i] = __float2bfloat16(src[i]);
}
__global__ void save_cls_kernel(const float* __restrict__ x, float* __restrict__ hist_r) {
    int i = blockIdx.x * 256 + threadIdx.x;
    if (i >= BB * DD) return;
    int b = i / DD, d = i % DD;
    hist_r[i] = x[(size_t)b * NN * DD + d];
}
__global__ void restore_patches_kernel(float* __restrict__ x, const float* __restrict__ x_in) {
    int i = blockIdx.x * 256 + threadIdx.x;
    if (i >= BB * NN * DD) return;
    int tok = (i / DD) % NN;
    if (tok != 0) x[i] = x_in[i];
}
__global__ void build_mem_bf_kernel(__nv_bfloat16* __restrict__ mem, const float* __restrict__ x,
                                    const float* __restrict__ hist, int Mk) {
    int i = blockIdx.x * 256 + threadIdx.x;
    if (i >= BB * Mk * DD) return;
    int d = i % DD;
    int t = (i / DD) % Mk;
    int b = i / (DD * Mk);
    float v;
    if (t < NN) v = x[((size_t)b * NN + t) * DD + d];
    else        v = hist[((size_t)(t - NN) * BB + b) * DD + d];
    mem[i] = __float2bfloat16(v);
}

// layernorm f32 in -> bf16 out, 1 warp per row
__global__ void ln_bf_kernel(const float* __restrict__ in, __nv_bfloat16* __restrict__ out,
                             const float* __restrict__ w, const float* __restrict__ b, int rows) {
    int row = blockIdx.x * 8 + (threadIdx.x >> 5);
    int lane = threadIdx.x & 31;
    if (row >= rows) return;
    const float* p = in + (size_t)row * DD;
    float v[12];
    float s = 0.f;
#pragma unroll
    for (int i = 0; i < 12; i++) { v[i] = p[lane + 32 * i]; s += v[i]; }
#pragma unroll
    for (int o = 16; o; o >>= 1) s += __shfl_xor_sync(0xffffffffu, s, o);
    float mu = s * (1.0f / DD);
    float var = 0.f;
#pragma unroll
    for (int i = 0; i < 12; i++) { float d = v[i] - mu; var += d * d; }
#pragma unroll
    for (int o = 16; o; o >>= 1) var += __shfl_xor_sync(0xffffffffu, var, o);
    float inv = rsqrtf(var * (1.0f / DD) + 1e-6f);
    __nv_bfloat16* q = out + (size_t)row * DD;
#pragma unroll
    for (int i = 0; i < 12; i++) {
        int c = lane + 32 * i;
        q[c] = __float2bfloat16((v[i] - mu) * inv * w[c] + b[c]);
    }
}

// softmax: f32 in (stride MPAD) -> bf16 out (stride MPAD, zero-padded), 1 warp/row
__global__ void softmax_bf_kernel(const float* __restrict__ s, __nv_bfloat16* __restrict__ out,
                                  int rows, int Mk) {
    int row = blockIdx.x * 8 + (threadIdx.x >> 5);
    int lane = threadIdx.x & 31;
    if (row >= rows) return;
    const float* p = s + (size_t)row * MPAD;
    float v[20];
    float mx = -1e30f;
#pragma unroll
    for (int i = 0; i < 20; i++) {
        int j = lane + 32 * i;
        v[i] = (j < Mk) ? p[j] : -1e30f;
        mx = fmaxf(mx, v[i]);
    }
#pragma unroll
    for (int o = 16; o; o >>= 1) mx = fmaxf(mx, __shfl_xor_sync(0xffffffffu, mx, o));
    float sum = 0.f;
#pragma unroll
    for (int i = 0; i < 20; i++) { v[i] = __expf(v[i] - mx); sum += v[i]; }
#pragma unroll
    for (int o = 16; o; o >>= 1) sum += __shfl_xor_sync(0xffffffffu, sum, o);
    float r = 1.0f / sum;
    __nv_bfloat16* q = out + (size_t)row * MPAD;
#pragma unroll
    for (int i = 0; i < 20; i++) {
        int j = lane + 32 * i;
        q[j] = __float2bfloat16((j < Mk) ? v[i] * r : 0.f);
    }
}

// ---------------- host orchestration ----------------
static inline int ceil_div(int a, int b) { return (a + b - 1) / b; }

extern "C" void kernel_launch(void* const* d_in, const int* in_sizes, int n_in,
                              void* d_out, int out_size) {
    const float* x_in    = (const float*)d_in[0];
    const float* norm1_w = (const float*)d_in[1];
    const float* norm1_b = (const float*)d_in[2];
    const float* qkv_w   = (const float*)d_in[3];
    const float* qkv_b   = (const float*)d_in[4];
    const float* qn_w    = (const float*)d_in[5];
    const float* qn_b    = (const float*)d_in[6];
    const float* kn_w    = (const float*)d_in[7];
    const float* kn_b    = (const float*)d_in[8];
    const float* an_w    = (const float*)d_in[9];
    const float* an_b    = (const float*)d_in[10];
    const float* proj_w  = (const float*)d_in[11];
    const float* proj_b  = (const float*)d_in[12];
    const float* ls1     = (const float*)d_in[13];
    const float* norm2_w = (const float*)d_in[14];
    const float* norm2_b = (const float*)d_in[15];
    const float* fc1_w   = (const float*)d_in[16];
    const float* fc1_b   = (const float*)d_in[17];
    const float* fc2_w   = (const float*)d_in[18];
    const float* fc2_b   = (const float*)d_in[19];
    const float* ls2     = (const float*)d_in[20];
    float* out = (float*)d_out;

    cudaFuncSetAttribute(mma_gemm_nt, cudaFuncAttributeMaxDynamicSharedMemorySize, SMEM_DYN);

    float *px, *pq, *pk, *pscores, *phist;
    __nv_bfloat16 *pmem, *pxn, *pqbf, *pkbf, *pvT, *pattn, *ppn, *ph;
    __nv_bfloat16 *wqkv, *wproj, *wfc1, *wfc2;
    cudaGetSymbolAddress((void**)&px, g_x);
    cudaGetSymbolAddress((void**)&pq, g_q);
    cudaGetSymbolAddress((void**)&pk, g_k);
    cudaGetSymbolAddress((void**)&pscores, g_scores);
    cudaGetSymbolAddress((void**)&phist, g_hist);
    cudaGetSymbolAddress((void**)&pmem, g_mem_bf);
    cudaGetSymbolAddress((void**)&pxn, g_xn_bf);
    cudaGetSymbolAddress((void**)&pqbf, g_qbf);
    cudaGetSymbolAddress((void**)&pkbf, g_kbf);
    cudaGetSymbolAddress((void**)&pvT, g_vT);
    cudaGetSymbolAddress((void**)&pattn, g_attn);
    cudaGetSymbolAddress((void**)&ppn, g_pn);
    cudaGetSymbolAddress((void**)&ph, g_h);
    cudaGetSymbolAddress((void**)&wqkv, g_wqkv);
    cudaGetSymbolAddress((void**)&wproj, g_wproj);
    cudaGetSymbolAddress((void**)&wfc1, g_wfc1);
    cudaGetSymbolAddress((void**)&wfc2, g_wfc2);

    const float scale = 1.0f / sqrtf((float)DD);
    const int nXND = BB * NN * DD;
    const int rowsX = BB * NN;

    // weight conversions (fp32 -> bf16)
    {
        int n1 = LL * 3 * DD * DD;
        cvt_bf_kernel<<<ceil_div(n1, 256), 256>>>(wqkv, qkv_w, n1);
        int n2 = LL * DD * DD;
        cvt_bf_kernel<<<ceil_div(n2, 256), 256>>>(wproj, proj_w, n2);
        int n3 = LL * HH * DD;
        cvt_bf_kernel<<<ceil_div(n3, 256), 256>>>(wfc1, fc1_w, n3);
        cvt_bf_kernel<<<ceil_div(n3, 256), 256>>>(wfc2, fc2_w, n3);
    }

    copy_kernel<<<ceil_div(nXND, 256), 256>>>(px, x_in, nXND);

    for (int r = 0; r < NRPT; r++) {
        int Mk = NN + r;
        int rowsM = BB * Mk;

        save_cls_kernel<<<ceil_div(BB * DD, 256), 256>>>(px, phist + (size_t)r * BB * DD);
        restore_patches_kernel<<<ceil_div(nXND, 256), 256>>>(px, x_in);
        build_mem_bf_kernel<<<ceil_div(BB * Mk * DD, 256), 256>>>(pmem, px, phist, Mk);

        int mtX = ceil_div(rowsX, 128);
        int mtM = ceil_div(rowsM, 128);
        int ntMk = ceil_div(Mk, 128);

        for (int l = 0; l < LL; l++) {
            const __nv_bfloat16* Wq = wqkv + (size_t)l * 3 * DD * DD;
            const __nv_bfloat16* Wk = Wq + (size_t)DD * DD;
            const __nv_bfloat16* Wv = Wq + (size_t)2 * DD * DD;
            const float* bq = qkv_b + (size_t)l * 3 * DD;
            const float* bk = bq + DD;
            const float* bv = bq + 2 * DD;

            // norm1 -> xn (bf16)
            ln_bf_kernel<<<ceil_div(rowsX, 8), 256>>>(px, pxn, norm1_w + l * DD, norm1_b + l * DD, rowsX);

            // q = xn @ Wq^T + bq  (f32)
            mma_gemm_nt<<<dim3(3, mtX, 1), 256, SMEM_DYN>>>(
                pxn, Wq, bq, 0, 0, pq, rowsX, DD, DD, DD, DD, DD, DD, 0, 0, 0, 1.0f, 0);
            // k = mem @ Wk^T + bk (f32)
            mma_gemm_nt<<<dim3(3, mtM, 1), 256, SMEM_DYN>>>(
                pmem, Wk, bk, 0, 0, pk, rowsM, DD, DD, DD, DD, DD, DD, 0, 0, 0, 1.0f, 0);
            // vT = Wv @ mem^T + bv(row)  -> bf16 [D, MPAD] per batch, pad zeros
            mma_gemm_nt<<<dim3(MPAD / 128, 3, BB), 256, SMEM_DYN>>>(
                Wv, pmem, bv, 0, 0, pvT, DD, Mk, MPAD, DD, DD, DD, MPAD,
                0, (long)Mk * DD, (long)DD * MPAD, 1.0f, 3);

            // q/k layernorms -> bf16
            ln_bf_kernel<<<ceil_div(rowsX, 8), 256>>>(pq, pqbf, qn_w + l * DD, qn_b + l * DD, rowsX);
            ln_bf_kernel<<<ceil_div(rowsM, 8), 256>>>(pk, pkbf, kn_w + l * DD, kn_b + l * DD, rowsM);

            // scores = scale * q @ k^T  (f32, per batch, ldc=MPAD)
            mma_gemm_nt<<<dim3(ntMk, ceil_div(NN, 128), BB), 256, SMEM_DYN>>>(
                pqbf, pkbf, 0, 0, 0, pscores, NN, Mk, Mk, DD, DD, DD, MPAD,
                (long)NN * DD, (long)Mk * DD, (long)NN * MPAD, scale, 0);
            softmax_bf_kernel<<<ceil_div(BB * NN, 8), 256>>>(pscores, pattn, BB * NN, Mk);

            // prod = attn @ vT^T  (f32, per batch; K = MPAD zero-padded)
            mma_gemm_nt<<<dim3(3, ceil_div(NN, 128), BB), 256, SMEM_DYN>>>(
                pattn, pvT, 0, 0, 0, pq, NN, DD, DD, MPAD, MPAD, MPAD, DD,
                (long)NN * MPAD, (long)DD * MPAD, (long)NN * DD, 1.0f, 0);

            // attn-out layernorm -> bf16
            ln_bf_kernel<<<ceil_div(rowsX, 8), 256>>>(pq, ppn, an_w + l * DD, an_b + l * DD, rowsX);

            // x += (prodn @ Wproj^T + bias) * ls1
            mma_gemm_nt<<<dim3(3, mtX, 1), 256, SMEM_DYN>>>(
                ppn, wproj + (size_t)l * DD * DD, proj_b + l * DD, ls1 + l * DD, px, px,
                rowsX, DD, DD, DD, DD, DD, DD, 0, 0, 0, 1.0f, 2);

            // MLP
            ln_bf_kernel<<<ceil_div(rowsX, 8), 256>>>(px, pxn, norm2_w + l * DD, norm2_b + l * DD, rowsX);
            mma_gemm_nt<<<dim3(HH / 128, mtX, 1), 256, SMEM_DYN>>>(
                pxn, wfc1 + (size_t)l * HH * DD, fc1_b + l * HH, 0, 0, ph,
                rowsX, HH, HH, DD, DD, DD, HH, 0, 0, 0, 1.0f, 1);
            mma_gemm_nt<<<dim3(3, mtX, 1), 256, SMEM_DYN>>>(
                ph, wfc2 + (size_t)l * DD * HH, fc2_b + l * DD, ls2 + l * DD, px, px,
                rowsX, DD, DD, HH, HH, HH, DD, 0, 0, 0, 1.0f, 2);
        }
    }

    copy_kernel<<<ceil_div(nXND, 256), 256>>>(out, px, nXND);
}

// round 6
// speedup vs baseline: 6.7934x; 2.2938x over previous
#include <cuda_runtime.h>
#include <cuda_bf16.h>
#include <math.h>
#include <stdint.h>

#define BB 32
#define NN 577
#define DD 384
#define LL 12
#define NRPT 4
#define HH 1536
#define MMAX 580
#define MPAD 640

// ---------------- scratch (static device arrays; no allocation) ----------------
__device__ float g_x[BB * NN * DD];
__device__ float g_q[BB * NN * DD];      // q GEMM out; reused for prod out
__device__ float g_k[BB * MMAX * DD];
__device__ float g_scores[(size_t)BB * NN * MPAD];
__device__ float g_hist[NRPT * BB * DD];
__device__ __nv_bfloat16 g_mem_bf[BB * MMAX * DD];
__device__ __nv_bfloat16 g_xn_bf[BB * NN * DD];
__device__ __nv_bfloat16 g_qbf[BB * NN * DD];
__device__ __nv_bfloat16 g_kbf[BB * MMAX * DD];
__device__ __nv_bfloat16 g_vT[BB * DD * MPAD];
__device__ __nv_bfloat16 g_attn[(size_t)BB * NN * MPAD];
__device__ __nv_bfloat16 g_pn[BB * NN * DD];
__device__ __nv_bfloat16 g_h[(size_t)BB * NN * HH];
__device__ __nv_bfloat16 g_wqkv[LL * 3 * DD * DD];
__device__ __nv_bfloat16 g_wproj[LL * DD * DD];
__device__ __nv_bfloat16 g_wfc1[LL * HH * DD];
__device__ __nv_bfloat16 g_wfc2[LL * DD * HH];

// ---------------- PTX helpers ----------------
__device__ __forceinline__ uint32_t smem_u32(const void* p) {
    uint32_t a;
    asm("{ .reg .u64 t; cvta.to.shared.u64 t, %1; cvt.u32.u64 %0, t; }" : "=r"(a) : "l"(p));
    return a;
}
__device__ __forceinline__ void cpasync16(uint32_t dst, const void* src, int srcsize) {
    asm volatile("cp.async.cg.shared.global [%0], [%1], 16, %2;" :: "r"(dst), "l"(src), "r"(srcsize));
}
__device__ __forceinline__ void cpcommit() { asm volatile("cp.async.commit_group;" ::: "memory"); }
__device__ __forceinline__ void cpwait1() { asm volatile("cp.async.wait_group 1;" ::: "memory"); }
__device__ __forceinline__ void cpwait0() { asm volatile("cp.async.wait_group 0;" ::: "memory"); }

#define LDSM4(r0, r1, r2, r3, a)                                                     \
    asm volatile("ldmatrix.sync.aligned.m8n8.x4.shared.b16 {%0,%1,%2,%3}, [%4];"     \
                 : "=r"(r0), "=r"(r1), "=r"(r2), "=r"(r3) : "r"(a))

#define MMA16816(d, av, bv)                                                          \
    asm volatile("mma.sync.aligned.m16n8k16.row.col.f32.bf16.bf16.f32 "              \
                 "{%0,%1,%2,%3},{%4,%5,%6,%7},{%8,%9},{%0,%1,%2,%3};"                \
                 : "+f"((d)[0]), "+f"((d)[1]), "+f"((d)[2]), "+f"((d)[3])            \
                 : "r"((av)[0]), "r"((av)[1]), "r"((av)[2]), "r"((av)[3]),           \
                   "r"((bv)[0]), "r"((bv)[1]))

// smem: 3 stages x (A[128][64]bf16 16KB + B[128][64]bf16 16KB)
#define SM_A(s) ((s) * 32768)
#define SM_B(s) ((s) * 32768 + 16384)
#define SMEM_DYN (3 * 32768 + 1024)

__device__ __forceinline__ float gelu_exact(float v) {
    return 0.5f * v * (1.0f + erff(v * 0.70710678118654752f));
}

// ---------------- HMMA GEMM: C[M,*] = A[M,K](bf16) @ W[N,K]^T(bf16) + epilogue ----------
// 256 threads = 8 warps (4 x 2). Tile 128x128, K-chunk 64, 3-stage cp.async ring.
// mode 0: f32 out, v = acc*alpha + bias[gn]     (bias may be null; odd Nvalid allowed if null)
// mode 1: bf16 out, v = gelu(acc + bias[gn])    (Nvalid % 128 == 0)
// mode 2: f32 out, v = (acc+bias[gn])*ls[gn] + res[gm*ldc+gn]   (Nvalid % 128 == 0)
// mode 3: bf16 out, v = acc + bias[gm]; zero-fill cols [Nvalid, Npad)  (Npad even)
__global__ void __launch_bounds__(256, 2)
mma_gemm_nt(const __nv_bfloat16* __restrict__ A, const __nv_bfloat16* __restrict__ W,
            const float* __restrict__ bias, const float* __restrict__ ls,
            const float* __restrict__ res, void* __restrict__ Cv,
            int Mrows, int Nvalid, int Npad, int K, int lda, int ldw, int ldc,
            long zA, long zW, long zC, float alpha, int mode) {
    extern __shared__ char smraw[];
    uint32_t sbase = (smem_u32(smraw) + 1023u) & ~1023u;
    int tid = threadIdx.x, wid = tid >> 5, lid = tid & 31;
    int bz = blockIdx.z;
    A += (size_t)bz * zA;
    W += (size_t)bz * zW;
    const float* resp = res ? res + (size_t)bz * zC : (const float*)0;
    int m0 = blockIdx.y * 128, n0 = blockIdx.x * 128;

    int wm = wid & 3;   // row group: wm*32
    int wn = wid >> 2;  // col group: wn*64

    float acc[2][8][4];
#pragma unroll
    for (int a = 0; a < 2; a++)
#pragma unroll
        for (int b = 0; b < 8; b++)
#pragma unroll
            for (int c = 0; c < 4; c++) acc[a][b][c] = 0.f;

    int nk = K >> 6;

#define LOAD_CHUNK(kc, s) do {                                                         \
    int _k0 = (kc) << 6;                                                               \
    _Pragma("unroll")                                                                  \
    for (int _i = 0; _i < 4; _i++) {                                                   \
        int _idx = tid + 256 * _i;                                                     \
        int _row = _idx >> 3, _g = _idx & 7;                                           \
        int _gm = m0 + _row;                                                           \
        int _pr = (_gm < Mrows) ? 16 : 0;                                              \
        const __nv_bfloat16* _src = A + (size_t)(_pr ? _gm : 0) * lda + _k0 + _g * 8;  \
        cpasync16(sbase + SM_A(s) + _row * 128 + (((_g ^ (_row & 7))) << 4), _src, _pr); \
    }                                                                                  \
    _Pragma("unroll")                                                                  \
    for (int _i = 0; _i < 4; _i++) {                                                   \
        int _idx = tid + 256 * _i;                                                     \
        int _row = _idx >> 3, _g = _idx & 7;                                           \
        int _gn = n0 + _row;                                                           \
        int _pr = (_gn < Nvalid) ? 16 : 0;                                             \
        const __nv_bfloat16* _src = W + (size_t)(_pr ? _gn : 0) * ldw + _k0 + _g * 8;  \
        cpasync16(sbase + SM_B(s) + _row * 128 + (((_g ^ (_row & 7))) << 4), _src, _pr); \
    }                                                                                  \
    cpcommit();                                                                        \
} while (0)

    // prologue: stages 0,1
    LOAD_CHUNK(0, 0);
    if (nk > 1) LOAD_CHUNK(1, 1);

    int grp = lid >> 3, rin = lid & 7;
    int slot = 0;
    for (int i = 0; i < nk; i++) {
        if (i + 1 < nk) cpwait1(); else cpwait0();
        __syncthreads();
        if (i + 2 < nk) {
            int ns = slot + 2; if (ns >= 3) ns -= 3;
            LOAD_CHUNK(i + 2, ns);
        }
        int s = slot;
#pragma unroll
        for (int ks = 0; ks < 4; ks++) {
            uint32_t af[2][4], bf[8][2];
#pragma unroll
            for (int mt = 0; mt < 2; mt++) {
                int row = wm * 32 + mt * 16 + rin + (grp & 1) * 8;
                int kg = ks * 2 + (grp >> 1);
                uint32_t ad = sbase + SM_A(s) + row * 128 + ((kg ^ (row & 7)) << 4);
                LDSM4(af[mt][0], af[mt][1], af[mt][2], af[mt][3], ad);
            }
#pragma unroll
            for (int np = 0; np < 4; np++) {
                int row = wn * 64 + np * 16 + rin + (grp >> 1) * 8;
                int kg = ks * 2 + (grp & 1);
                uint32_t ad = sbase + SM_B(s) + row * 128 + ((kg ^ (row & 7)) << 4);
                LDSM4(bf[2 * np][0], bf[2 * np][1], bf[2 * np + 1][0], bf[2 * np + 1][1], ad);
            }
#pragma unroll
            for (int mt = 0; mt < 2; mt++)
#pragma unroll
                for (int nt = 0; nt < 8; nt++)
                    MMA16816(acc[mt][nt], af[mt], bf[nt]);
        }
        slot++; if (slot >= 3) slot = 0;
    }

    // ------------- vectorized epilogue -------------
#pragma unroll
    for (int mt = 0; mt < 2; mt++) {
        int rbase = m0 + wm * 32 + mt * 16 + (lid >> 2);
#pragma unroll
        for (int nt = 0; nt < 8; nt++) {
            int c0 = n0 + wn * 64 + nt * 8 + (lid & 3) * 2;
#pragma unroll
            for (int half = 0; half < 2; half++) {
                int gm = rbase + half * 8;
                if (gm >= Mrows) continue;
                float a0 = acc[mt][nt][half * 2], a1 = acc[mt][nt][half * 2 + 1];
                if (mode == 0) {
                    float* C = (float*)Cv + (size_t)bz * zC;
                    if (bias) {
                        float2 v = make_float2(a0 * alpha + bias[c0], a1 * alpha + bias[c0 + 1]);
                        *(float2*)(C + (size_t)gm * ldc + c0) = v;
                    } else {
                        if (c0 + 1 < Nvalid) {
                            float2 v = make_float2(a0 * alpha, a1 * alpha);
                            *(float2*)(C + (size_t)gm * ldc + c0) = v;
                        } else if (c0 < Nvalid) {
                            C[(size_t)gm * ldc + c0] = a0 * alpha;
                        }
                    }
                } else if (mode == 1) {
                    __nv_bfloat16* C = (__nv_bfloat16*)Cv + (size_t)bz * zC;
                    __nv_bfloat162 v;
                    v.x = __float2bfloat16(gelu_exact(a0 + bias[c0]));
                    v.y = __float2bfloat16(gelu_exact(a1 + bias[c0 + 1]));
                    *(__nv_bfloat162*)(C + (size_t)gm * ldc + c0) = v;
                } else if (mode == 2) {
                    float* C = (float*)Cv + (size_t)bz * zC;
                    float2 r = *(const float2*)(resp + (size_t)gm * ldc + c0);
                    float2 v = make_float2((a0 + bias[c0]) * ls[c0] + r.x,
                                           (a1 + bias[c0 + 1]) * ls[c0 + 1] + r.y);
                    *(float2*)(C + (size_t)gm * ldc + c0) = v;
                } else {
                    __nv_bfloat16* C = (__nv_bfloat16*)Cv + (size_t)bz * zC;
                    float bb = bias ? bias[gm] : 0.f;
                    __nv_bfloat162 v;
                    v.x = __float2bfloat16((c0 < Nvalid) ? (a0 + bb) : 0.f);
                    v.y = __float2bfloat16((c0 + 1 < Nvalid) ? (a1 + bb) : 0.f);
                    if (c0 + 1 < Npad)
                        *(__nv_bfloat162*)(C + (size_t)gm * ldc + c0) = v;
                }
            }
        }
    }
}

// ---------------- small kernels ----------------
__global__ void copy_kernel(float* __restrict__ dst, const float* __restrict__ src, int n) {
    int i = blockIdx.x * 256 + threadIdx.x;
    if (i < n) dst[i] = src[i];
}
__global__ void cvt_bf_kernel(__nv_bfloat16* __restrict__ dst, const float* __restrict__ src, int n) {
    int i = blockIdx.x * 256 + threadIdx.x;
    if (i < n) dst[i] = __float2bfloat16(src[i]);
}
__global__ void save_cls_kernel(const float* __restrict__ x, float* __restrict__ hist_r) {
    int i = blockIdx.x * 256 + threadIdx.x;
    if (i >= BB * DD) return;
    int b = i / DD, d = i % DD;
    hist_r[i] = x[(size_t)b * NN * DD + d];
}
__global__ void restore_patches_kernel(float* __restrict__ x, const float* __restrict__ x_in) {
    int i = blockIdx.x * 256 + threadIdx.x;
    if (i >= BB * NN * DD) return;
    int tok = (i / DD) % NN;
    if (tok != 0) x[i] = x_in[i];
}
__global__ void build_mem_bf_kernel(__nv_bfloat16* __restrict__ mem, const float* __restrict__ x,
                                    const float* __restrict__ hist, int Mk) {
    int i = blockIdx.x * 256 + threadIdx.x;
    if (i >= BB * Mk * DD) return;
    int d = i % DD;
    int t = (i / DD) % Mk;
    int b = i / (DD * Mk);
    float v;
    if (t < NN) v = x[((size_t)b * NN + t) * DD + d];
    else        v = hist[((size_t)(t - NN) * BB + b) * DD + d];
    mem[i] = __float2bfloat16(v);
}

// layernorm f32 in -> bf16 out, 1 warp per row (vectorized: float2 / bf162)
__global__ void ln_bf_kernel(const float* __restrict__ in, __nv_bfloat16* __restrict__ out,
                             const float* __restrict__ w, const float* __restrict__ b, int rows) {
    int row = blockIdx.x * 8 + (threadIdx.x >> 5);
    int lane = threadIdx.x & 31;
    if (row >= rows) return;
    const float2* p = (const float2*)(in + (size_t)row * DD);
    float2 v[6];
    float s = 0.f;
#pragma unroll
    for (int i = 0; i < 6; i++) { v[i] = p[lane + 32 * i]; s += v[i].x + v[i].y; }
#pragma unroll
    for (int o = 16; o; o >>= 1) s += __shfl_xor_sync(0xffffffffu, s, o);
    float mu = s * (1.0f / DD);
    float var = 0.f;
#pragma unroll
    for (int i = 0; i < 6; i++) {
        float dx = v[i].x - mu, dy = v[i].y - mu;
        var += dx * dx + dy * dy;
    }
#pragma unroll
    for (int o = 16; o; o >>= 1) var += __shfl_xor_sync(0xffffffffu, var, o);
    float inv = rsqrtf(var * (1.0f / DD) + 1e-6f);
    __nv_bfloat162* q = (__nv_bfloat162*)(out + (size_t)row * DD);
    const float2* w2 = (const float2*)w;
    const float2* b2 = (const float2*)b;
#pragma unroll
    for (int i = 0; i < 6; i++) {
        int c = lane + 32 * i;
        float2 ww = w2[c], bb = b2[c];
        __nv_bfloat162 o2;
        o2.x = __float2bfloat16((v[i].x - mu) * inv * ww.x + bb.x);
        o2.y = __float2bfloat16((v[i].y - mu) * inv * ww.y + bb.y);
        q[c] = o2;
    }
}

// softmax: f32 in (stride MPAD) -> bf16 out (stride MPAD, zero-padded), 1 warp/row
__global__ void softmax_bf_kernel(const float* __restrict__ s, __nv_bfloat16* __restrict__ out,
                                  int rows, int Mk) {
    int row = blockIdx.x * 8 + (threadIdx.x >> 5);
    int lane = threadIdx.x & 31;
    if (row >= rows) return;
    const float2* p = (const float2*)(s + (size_t)row * MPAD);
    float2 v[10];
    float mx = -1e30f;
#pragma unroll
    for (int i = 0; i < 10; i++) {
        int j = 2 * (lane + 32 * i);
        float2 t = p[lane + 32 * i];
        v[i].x = (j < Mk) ? t.x : -1e30f;
        v[i].y = (j + 1 < Mk) ? t.y : -1e30f;
        mx = fmaxf(mx, fmaxf(v[i].x, v[i].y));
    }
#pragma unroll
    for (int o = 16; o; o >>= 1) mx = fmaxf(mx, __shfl_xor_sync(0xffffffffu, mx, o));
    float sum = 0.f;
#pragma unroll
    for (int i = 0; i < 10; i++) {
        v[i].x = __expf(v[i].x - mx);
        v[i].y = __expf(v[i].y - mx);
        sum += v[i].x + v[i].y;
    }
#pragma unroll
    for (int o = 16; o; o >>= 1) sum += __shfl_xor_sync(0xffffffffu, sum, o);
    float r = 1.0f / sum;
    __nv_bfloat162* q = (__nv_bfloat162*)(out + (size_t)row * MPAD);
#pragma unroll
    for (int i = 0; i < 10; i++) {
        int j = 2 * (lane + 32 * i);
        __nv_bfloat162 o2;
        o2.x = __float2bfloat16((j < Mk) ? v[i].x * r : 0.f);
        o2.y = __float2bfloat16((j + 1 < Mk) ? v[i].y * r : 0.f);
        q[lane + 32 * i] = o2;
    }
}

// ---------------- host orchestration ----------------
static inline int ceil_div(int a, int b) { return (a + b - 1) / b; }

extern "C" void kernel_launch(void* const* d_in, const int* in_sizes, int n_in,
                              void* d_out, int out_size) {
    const float* x_in    = (const float*)d_in[0];
    const float* norm1_w = (const float*)d_in[1];
    const float* norm1_b = (const float*)d_in[2];
    const float* qkv_w   = (const float*)d_in[3];
    const float* qkv_b   = (const float*)d_in[4];
    const float* qn_w    = (const float*)d_in[5];
    const float* qn_b    = (const float*)d_in[6];
    const float* kn_w    = (const float*)d_in[7];
    const float* kn_b    = (const float*)d_in[8];
    const float* an_w    = (const float*)d_in[9];
    const float* an_b    = (const float*)d_in[10];
    const float* proj_w  = (const float*)d_in[11];
    const float* proj_b  = (const float*)d_in[12];
    const float* ls1     = (const float*)d_in[13];
    const float* norm2_w = (const float*)d_in[14];
    const float* norm2_b = (const float*)d_in[15];
    const float* fc1_w   = (const float*)d_in[16];
    const float* fc1_b   = (const float*)d_in[17];
    const float* fc2_w   = (const float*)d_in[18];
    const float* fc2_b   = (const float*)d_in[19];
    const float* ls2     = (const float*)d_in[20];
    float* out = (float*)d_out;

    cudaFuncSetAttribute(mma_gemm_nt, cudaFuncAttributeMaxDynamicSharedMemorySize, SMEM_DYN);

    float *px, *pq, *pk, *pscores, *phist;
    __nv_bfloat16 *pmem, *pxn, *pqbf, *pkbf, *pvT, *pattn, *ppn, *ph;
    __nv_bfloat16 *wqkv, *wproj, *wfc1, *wfc2;
    cudaGetSymbolAddress((void**)&px, g_x);
    cudaGetSymbolAddress((void**)&pq, g_q);
    cudaGetSymbolAddress((void**)&pk, g_k);
    cudaGetSymbolAddress((void**)&pscores, g_scores);
    cudaGetSymbolAddress((void**)&phist, g_hist);
    cudaGetSymbolAddress((void**)&pmem, g_mem_bf);
    cudaGetSymbolAddress((void**)&pxn, g_xn_bf);
    cudaGetSymbolAddress((void**)&pqbf, g_qbf);
    cudaGetSymbolAddress((void**)&pkbf, g_kbf);
    cudaGetSymbolAddress((void**)&pvT, g_vT);
    cudaGetSymbolAddress((void**)&pattn, g_attn);
    cudaGetSymbolAddress((void**)&ppn, g_pn);
    cudaGetSymbolAddress((void**)&ph, g_h);
    cudaGetSymbolAddress((void**)&wqkv, g_wqkv);
    cudaGetSymbolAddress((void**)&wproj, g_wproj);
    cudaGetSymbolAddress((void**)&wfc1, g_wfc1);
    cudaGetSymbolAddress((void**)&wfc2, g_wfc2);

    const float scale = 1.0f / sqrtf((float)DD);
    const int nXND = BB * NN * DD;
    const int rowsX = BB * NN;

    // weight conversions (fp32 -> bf16)
    {
        int n1 = LL * 3 * DD * DD;
        cvt_bf_kernel<<<ceil_div(n1, 256), 256>>>(wqkv, qkv_w, n1);
        int n2 = LL * DD * DD;
        cvt_bf_kernel<<<ceil_div(n2, 256), 256>>>(wproj, proj_w, n2);
        int n3 = LL * HH * DD;
        cvt_bf_kernel<<<ceil_div(n3, 256), 256>>>(wfc1, fc1_w, n3);
        cvt_bf_kernel<<<ceil_div(n3, 256), 256>>>(wfc2, fc2_w, n3);
    }

    copy_kernel<<<ceil_div(nXND, 256), 256>>>(px, x_in, nXND);

    for (int r = 0; r < NRPT; r++) {
        int Mk = NN + r;
        int rowsM = BB * Mk;

        save_cls_kernel<<<ceil_div(BB * DD, 256), 256>>>(px, phist + (size_t)r * BB * DD);
        restore_patches_kernel<<<ceil_div(nXND, 256), 256>>>(px, x_in);
        build_mem_bf_kernel<<<ceil_div(BB * Mk * DD, 256), 256>>>(pmem, px, phist, Mk);

        int mtX = ceil_div(rowsX, 128);
        int mtM = ceil_div(rowsM, 128);
        int ntMk = ceil_div(Mk, 128);

        for (int l = 0; l < LL; l++) {
            const __nv_bfloat16* Wq = wqkv + (size_t)l * 3 * DD * DD;
            const __nv_bfloat16* Wk = Wq + (size_t)DD * DD;
            const __nv_bfloat16* Wv = Wq + (size_t)2 * DD * DD;
            const float* bq = qkv_b + (size_t)l * 3 * DD;
            const float* bk = bq + DD;
            const float* bv = bq + 2 * DD;

            // norm1 -> xn (bf16)
            ln_bf_kernel<<<ceil_div(rowsX, 8), 256>>>(px, pxn, norm1_w + l * DD, norm1_b + l * DD, rowsX);

            // q = xn @ Wq^T + bq  (f32)
            mma_gemm_nt<<<dim3(3, mtX, 1), 256, SMEM_DYN>>>(
                pxn, Wq, bq, 0, 0, pq, rowsX, DD, DD, DD, DD, DD, DD, 0, 0, 0, 1.0f, 0);
            // k = mem @ Wk^T + bk (f32)
            mma_gemm_nt<<<dim3(3, mtM, 1), 256, SMEM_DYN>>>(
                pmem, Wk, bk, 0, 0, pk, rowsM, DD, DD, DD, DD, DD, DD, 0, 0, 0, 1.0f, 0);
            // vT = Wv @ mem^T + bv(row)  -> bf16 [D, MPAD] per batch, pad zeros
            mma_gemm_nt<<<dim3(MPAD / 128, 3, BB), 256, SMEM_DYN>>>(
                Wv, pmem, bv, 0, 0, pvT, DD, Mk, MPAD, DD, DD, DD, MPAD,
                0, (long)Mk * DD, (long)DD * MPAD, 1.0f, 3);

            // q/k layernorms -> bf16
            ln_bf_kernel<<<ceil_div(rowsX, 8), 256>>>(pq, pqbf, qn_w + l * DD, qn_b + l * DD, rowsX);
            ln_bf_kernel<<<ceil_div(rowsM, 8), 256>>>(pk, pkbf, kn_w + l * DD, kn_b + l * DD, rowsM);

            // scores = scale * q @ k^T  (f32, per batch, ldc=MPAD)
            mma_gemm_nt<<<dim3(ntMk, ceil_div(NN, 128), BB), 256, SMEM_DYN>>>(
                pqbf, pkbf, 0, 0, 0, pscores, NN, Mk, Mk, DD, DD, DD, MPAD,
                (long)NN * DD, (long)Mk * DD, (long)NN * MPAD, scale, 0);
            softmax_bf_kernel<<<ceil_div(BB * NN, 8), 256>>>(pscores, pattn, BB * NN, Mk);

            // prod = attn @ vT^T  (f32, per batch; K = MPAD zero-padded)
            mma_gemm_nt<<<dim3(3, ceil_div(NN, 128), BB), 256, SMEM_DYN>>>(
                pattn, pvT, 0, 0, 0, pq, NN, DD, DD, MPAD, MPAD, MPAD, DD,
                (long)NN * MPAD, (long)DD * MPAD, (long)NN * DD, 1.0f, 0);

            // attn-out layernorm -> bf16
            ln_bf_kernel<<<ceil_div(rowsX, 8), 256>>>(pq, ppn, an_w + l * DD, an_b + l * DD, rowsX);

            // x += (prodn @ Wproj^T + bias) * ls1
            mma_gemm_nt<<<dim3(3, mtX, 1), 256, SMEM_DYN>>>(
                ppn, wproj + (size_t)l * DD * DD, proj_b + l * DD, ls1 + l * DD, px, px,
                rowsX, DD, DD, DD, DD, DD, DD, 0, 0, 0, 1.0f, 2);

            // MLP
            ln_bf_kernel<<<ceil_div(rowsX, 8), 256>>>(px, pxn, norm2_w + l * DD, norm2_b + l * DD, rowsX);
            mma_gemm_nt<<<dim3(HH / 128, mtX, 1), 256, SMEM_DYN>>>(
                pxn, wfc1 + (size_t)l * HH * DD, fc1_b + l * HH, 0, 0, ph,
                rowsX, HH, HH, DD, DD, DD, HH, 0, 0, 0, 1.0f, 1);
            mma_gemm_nt<<<dim3(3, mtX, 1), 256, SMEM_DYN>>>(
                ph, wfc2 + (size_t)l * DD * HH, fc2_b + l * DD, ls2 + l * DD, px, px,
                rowsX, DD, DD, HH, HH, HH, DD, 0, 0, 0, 1.0f, 2);
        }
    }

    copy_kernel<<<ceil_div(nXND, 256), 256>>>(out, px, nXND);
}

// round 10
// speedup vs baseline: 6.8124x; 1.0028x over previous
#include <cuda_runtime.h>
#include <cuda_bf16.h>
#include <math.h>
#include <stdint.h>

#define BB 32
#define NN 577
#define DD 384
#define LL 12
#define NRPT 4
#define HH 1536
#define MMAX 580
#define MPAD 640

// ---------------- scratch (static device arrays; no allocation) ----------------
__device__ float g_x[BB * NN * DD];
__device__ float g_q[BB * NN * DD];      // q GEMM out; reused for prod out
__device__ float g_k[BB * MMAX * DD];
__device__ float g_scores[(size_t)BB * NN * MPAD];
__device__ float g_hist[NRPT * BB * DD];
// fp8 operand buffers
__device__ uint8_t g_mem8[BB * MMAX * DD];
__device__ uint8_t g_xn8[BB * NN * DD];
__device__ uint8_t g_q8[BB * NN * DD];
__device__ uint8_t g_k8[BB * MMAX * DD];
__device__ uint8_t g_vT8[BB * DD * MPAD];
__device__ uint8_t g_attn8[(size_t)BB * NN * MPAD];
__device__ uint8_t g_pn8[BB * NN * DD];
__device__ uint8_t g_h8[(size_t)BB * NN * HH];
__device__ uint8_t g_wqkv8[LL * 3 * DD * DD];
__device__ uint8_t g_wproj8[LL * DD * DD];
__device__ uint8_t g_wfc18[LL * HH * DD];
__device__ uint8_t g_wfc28[LL * DD * HH];

// operand scales (powers of 2)
#define SC_W 32.0f
#define SC_LN 4.0f
#define SC_MEM 4.0f
#define SC_ATTN 16.0f
#define SC_V 8.0f
#define SC_H 16.0f

// ---------------- PTX helpers ----------------
__device__ __forceinline__ uint32_t smem_u32(const void* p) {
    uint32_t a;
    asm("{ .reg .u64 t; cvta.to.shared.u64 t, %1; cvt.u32.u64 %0, t; }" : "=r"(a) : "l"(p));
    return a;
}
__device__ __forceinline__ void cpasync16(uint32_t dst, const void* src, int srcsize) {
    asm volatile("cp.async.cg.shared.global [%0], [%1], 16, %2;" :: "r"(dst), "l"(src), "r"(srcsize));
}
__device__ __forceinline__ void cpcommit() { asm volatile("cp.async.commit_group;" ::: "memory"); }
__device__ __forceinline__ void cpwait1() { asm volatile("cp.async.wait_group 1;" ::: "memory"); }
__device__ __forceinline__ void cpwait0() { asm volatile("cp.async.wait_group 0;" ::: "memory"); }

// pack two floats -> e4m3x2 (lo in low byte, hi in high byte); satfinite clamps
__device__ __forceinline__ uint16_t pack_e4m3(float lo, float hi) {
    uint16_t r;
    asm("cvt.rn.satfinite.e4m3x2.f32 %0, %1, %2;" : "=h"(r) : "f"(hi), "f"(lo));
    return r;
}

#define LDSM4(r0, r1, r2, r3, a)                                                     \
    asm volatile("ldmatrix.sync.aligned.m8n8.x4.shared.b16 {%0,%1,%2,%3}, [%4];"     \
                 : "=r"(r0), "=r"(r1), "=r"(r2), "=r"(r3) : "r"(a))

#define MMAFP8(d, av, bv)                                                            \
    asm volatile("mma.sync.aligned.m16n8k32.row.col.f32.e4m3.e4m3.f32 "              \
                 "{%0,%1,%2,%3},{%4,%5,%6,%7},{%8,%9},{%0,%1,%2,%3};"                \
                 : "+f"((d)[0]), "+f"((d)[1]), "+f"((d)[2]), "+f"((d)[3])            \
                 : "r"((av)[0]), "r"((av)[1]), "r"((av)[2]), "r"((av)[3]),           \
                   "r"((bv)[0]), "r"((bv)[1]))

// smem: 3 stages x (A[128][128]fp8 16KB + B[128][128]fp8 16KB)
#define SM_A(s) ((s) * 32768)
#define SM_B(s) ((s) * 32768 + 16384)
#define SMEM_DYN (3 * 32768 + 1024)

__device__ __forceinline__ float gelu_exact(float v) {
    return 0.5f * v * (1.0f + erff(v * 0.70710678118654752f));
}

// ---------------- FP8 HMMA GEMM: C[M,*] = A[M,K](e4m3) @ W[N,K]^T(e4m3) + epilogue -----
// 256 threads = 8 warps (4 x 2). Tile 128x128, K-chunk 128, 3-stage cp.async ring.
// All modes: base = acc*alpha + bias
// mode 0: f32 out, bias[gn] (may be null; odd Nvalid allowed iff null)
// mode 1: fp8 out, v = gelu(base)*oscale          (Nvalid % 128 == 0)
// mode 2: f32 out, v = base*ls[gn] + res[..]      (Nvalid % 128 == 0)
// mode 3: fp8 out, v = base*oscale, bias[gm]; zero-fill cols [Nvalid, Npad) (Npad even)
__global__ void __launch_bounds__(256, 2)
mma_gemm_nt(const uint8_t* __restrict__ A, const uint8_t* __restrict__ W,
            const float* __restrict__ bias, const float* __restrict__ ls,
            const float* __restrict__ res, void* __restrict__ Cv,
            int Mrows, int Nvalid, int Npad, int K, int lda, int ldw, int ldc,
            long zA, long zW, long zC, float alpha, float oscale, int mode) {
    extern __shared__ char smraw[];
    uint32_t sbase = (smem_u32(smraw) + 1023u) & ~1023u;
    int tid = threadIdx.x, wid = tid >> 5, lid = tid & 31;
    int bz = blockIdx.z;
    A += (size_t)bz * zA;
    W += (size_t)bz * zW;
    const float* resp = res ? res + (size_t)bz * zC : (const float*)0;
    int m0 = blockIdx.y * 128, n0 = blockIdx.x * 128;

    int wm = wid & 3;   // row group: wm*32
    int wn = wid >> 2;  // col group: wn*64

    float acc[2][8][4];
#pragma unroll
    for (int a = 0; a < 2; a++)
#pragma unroll
        for (int b = 0; b < 8; b++)
#pragma unroll
            for (int c = 0; c < 4; c++) acc[a][b][c] = 0.f;

    int nk = K >> 7;   // K-chunk = 128 fp8 = 128 B/row

#define LOAD_CHUNK(kc, s) do {                                                         \
    int _k0 = (kc) << 7;                                                               \
    _Pragma("unroll")                                                                  \
    for (int _i = 0; _i < 4; _i++) {                                                   \
        int _idx = tid + 256 * _i;                                                     \
        int _row = _idx >> 3, _g = _idx & 7;                                           \
        int _gm = m0 + _row;                                                           \
        int _pr = (_gm < Mrows) ? 16 : 0;                                              \
        const uint8_t* _src = A + (size_t)(_pr ? _gm : 0) * lda + _k0 + _g * 16;       \
        cpasync16(sbase + SM_A(s) + _row * 128 + (((_g ^ (_row & 7))) << 4), _src, _pr); \
    }                                                                                  \
    _Pragma("unroll")                                                                  \
    for (int _i = 0; _i < 4; _i++) {                                                   \
        int _idx = tid + 256 * _i;                                                     \
        int _row = _idx >> 3, _g = _idx & 7;                                           \
        int _gn = n0 + _row;                                                           \
        int _pr = (_gn < Nvalid) ? 16 : 0;                                             \
        const uint8_t* _src = W + (size_t)(_pr ? _gn : 0) * ldw + _k0 + _g * 16;       \
        cpasync16(sbase + SM_B(s) + _row * 128 + (((_g ^ (_row & 7))) << 4), _src, _pr); \
    }                                                                                  \
    cpcommit();                                                                        \
} while (0)

    LOAD_CHUNK(0, 0);
    if (nk > 1) LOAD_CHUNK(1, 1);

    int grp = lid >> 3, rin = lid & 7;
    int slot = 0;
    for (int i = 0; i < nk; i++) {
        if (i + 1 < nk) cpwait1(); else cpwait0();
        __syncthreads();
        if (i + 2 < nk) {
            int ns = slot + 2; if (ns >= 3) ns -= 3;
            LOAD_CHUNK(i + 2, ns);
        }
        int s = slot;
#pragma unroll
        for (int ks = 0; ks < 4; ks++) {   // each ks = 32 fp8 of K (2 granules of 16B)
            uint32_t af[2][4], bf[8][2];
#pragma unroll
            for (int mt = 0; mt < 2; mt++) {
                int row = wm * 32 + mt * 16 + rin + (grp & 1) * 8;
                int kg = ks * 2 + (grp >> 1);
                uint32_t ad = sbase + SM_A(s) + row * 128 + ((kg ^ (row & 7)) << 4);
                LDSM4(af[mt][0], af[mt][1], af[mt][2], af[mt][3], ad);
            }
#pragma unroll
            for (int np = 0; np < 4; np++) {
                int row = wn * 64 + np * 16 + rin + (grp >> 1) * 8;
                int kg = ks * 2 + (grp & 1);
                uint32_t ad = sbase + SM_B(s) + row * 128 + ((kg ^ (row & 7)) << 4);
                LDSM4(bf[2 * np][0], bf[2 * np][1], bf[2 * np + 1][0], bf[2 * np + 1][1], ad);
            }
#pragma unroll
            for (int mt = 0; mt < 2; mt++)
#pragma unroll
                for (int nt = 0; nt < 8; nt++)
                    MMAFP8(acc[mt][nt], af[mt], bf[nt]);
        }
        slot++; if (slot >= 3) slot = 0;
    }

    // ------------- vectorized epilogue -------------
#pragma unroll
    for (int mt = 0; mt < 2; mt++) {
        int rbase = m0 + wm * 32 + mt * 16 + (lid >> 2);
#pragma unroll
        for (int nt = 0; nt < 8; nt++) {
            int c0 = n0 + wn * 64 + nt * 8 + (lid & 3) * 2;
#pragma unroll
            for (int half = 0; half < 2; half++) {
                int gm = rbase + half * 8;
                if (gm >= Mrows) continue;
                float a0 = acc[mt][nt][half * 2] * alpha;
                float a1 = acc[mt][nt][half * 2 + 1] * alpha;
                if (mode == 0) {
                    float* C = (float*)Cv + (size_t)bz * zC;
                    if (bias) {
                        float2 v = make_float2(a0 + bias[c0], a1 + bias[c0 + 1]);
                        *(float2*)(C + (size_t)gm * ldc + c0) = v;
                    } else {
                        if (c0 + 1 < Nvalid) {
                            *(float2*)(C + (size_t)gm * ldc + c0) = make_float2(a0, a1);
                        } else if (c0 < Nvalid) {
                            C[(size_t)gm * ldc + c0] = a0;
                        }
                    }
                } else if (mode == 1) {
                    uint8_t* C = (uint8_t*)Cv + (size_t)bz * zC;
                    float v0 = gelu_exact(a0 + bias[c0]) * oscale;
                    float v1 = gelu_exact(a1 + bias[c0 + 1]) * oscale;
                    *(uint16_t*)(C + (size_t)gm * ldc + c0) = pack_e4m3(v0, v1);
                } else if (mode == 2) {
                    float* C = (float*)Cv + (size_t)bz * zC;
                    float2 r = *(const float2*)(resp + (size_t)gm * ldc + c0);
                    float2 v = make_float2((a0 + bias[c0]) * ls[c0] + r.x,
                                           (a1 + bias[c0 + 1]) * ls[c0 + 1] + r.y);
                    *(float2*)(C + (size_t)gm * ldc + c0) = v;
                } else {
                    uint8_t* C = (uint8_t*)Cv + (size_t)bz * zC;
                    float bb = bias ? bias[gm] : 0.f;
                    float v0 = (c0 < Nvalid) ? (a0 + bb) * oscale : 0.f;
                    float v1 = (c0 + 1 < Nvalid) ? (a1 + bb) * oscale : 0.f;
                    if (c0 + 1 < Npad)
                        *(uint16_t*)(C + (size_t)gm * ldc + c0) = pack_e4m3(v0, v1);
                }
            }
        }
    }
}

// ---------------- small kernels ----------------
__global__ void copy_kernel(float* __restrict__ dst, const float* __restrict__ src, int n) {
    int i = blockIdx.x * 256 + threadIdx.x;
    if (i < n) dst[i] = src[i];
}
// fp32 -> e4m3 (x SC_W), pairs
__global__ void cvt_w8_kernel(uint8_t* __restrict__ dst, const float* __restrict__ src, int npair) {
    int i = blockIdx.x * 256 + threadIdx.x;
    if (i >= npair) return;
    float2 v = *(const float2*)(src + 2 * i);
    *(uint16_t*)(dst + 2 * i) = pack_e4m3(v.x * SC_W, v.y * SC_W);
}
__global__ void save_cls_kernel(const float* __restrict__ x, float* __restrict__ hist_r) {
    int i = blockIdx.x * 256 + threadIdx.x;
    if (i >= BB * DD) return;
    int b = i / DD, d = i % DD;
    hist_r[i] = x[(size_t)b * NN * DD + d];
}
__global__ void restore_patches_kernel(float* __restrict__ x, const float* __restrict__ x_in) {
    int i = blockIdx.x * 256 + threadIdx.x;
    if (i >= BB * NN * DD) return;
    int tok = (i / DD) % NN;
    if (tok != 0) x[i] = x_in[i];
}
// mem (f32 gather) -> fp8 x SC_MEM, pair-per-thread
__global__ void build_mem8_kernel(uint8_t* __restrict__ mem, const float* __restrict__ x,
                                  const float* __restrict__ hist, int Mk) {
    int i = blockIdx.x * 256 + threadIdx.x;   // pair index
    int npair = BB * Mk * (DD / 2);
    if (i >= npair) return;
    int d2 = i % (DD / 2);
    int t = (i / (DD / 2)) % Mk;
    int b = i / ((DD / 2) * Mk);
    const float* src;
    if (t < NN) src = x + ((size_t)b * NN + t) * DD + 2 * d2;
    else        src = hist + ((size_t)(t - NN) * BB + b) * DD + 2 * d2;
    float2 v = *(const float2*)src;
    *(uint16_t*)(mem + ((size_t)b * Mk + t) * DD + 2 * d2) = pack_e4m3(v.x * SC_MEM, v.y * SC_MEM);
}

// layernorm f32 in -> e4m3 out (x SC_LN), 1 warp per row
__global__ void ln_f8_kernel(const float* __restrict__ in, uint8_t* __restrict__ out,
                             const float* __restrict__ w, const float* __restrict__ b, int rows) {
    int row = blockIdx.x * 8 + (threadIdx.x >> 5);
    int lane = threadIdx.x & 31;
    if (row >= rows) return;
    const float2* p = (const float2*)(in + (size_t)row * DD);
    float2 v[6];
    float s = 0.f;
#pragma unroll
    for (int i = 0; i < 6; i++) { v[i] = p[lane + 32 * i]; s += v[i].x + v[i].y; }
#pragma unroll
    for (int o = 16; o; o >>= 1) s += __shfl_xor_sync(0xffffffffu, s, o);
    float mu = s * (1.0f / DD);
    float var = 0.f;
#pragma unroll
    for (int i = 0; i < 6; i++) {
        float dx = v[i].x - mu, dy = v[i].y - mu;
        var += dx * dx + dy * dy;
    }
#pragma unroll
    for (int o = 16; o; o >>= 1) var += __shfl_xor_sync(0xffffffffu, var, o);
    float inv = rsqrtf(var * (1.0f / DD) + 1e-6f);
    uint8_t* q = out + (size_t)row * DD;
    const float2* w2 = (const float2*)w;
    const float2* b2 = (const float2*)b;
#pragma unroll
    for (int i = 0; i < 6; i++) {
        int c = lane + 32 * i;
        float2 ww = w2[c], bb = b2[c];
        float o0 = ((v[i].x - mu) * inv * ww.x + bb.x) * SC_LN;
        float o1 = ((v[i].y - mu) * inv * ww.y + bb.y) * SC_LN;
        *(uint16_t*)(q + 2 * c) = pack_e4m3(o0, o1);
    }
}

// softmax: f32 in (stride MPAD) -> e4m3 out x SC_ATTN (stride MPAD, zero-padded), 1 warp/row
__global__ void softmax_f8_kernel(const float* __restrict__ s, uint8_t* __restrict__ out,
                                  int rows, int Mk) {
    int row = blockIdx.x * 8 + (threadIdx.x >> 5);
    int lane = threadIdx.x & 31;
    if (row >= rows) return;
    const float2* p = (const float2*)(s + (size_t)row * MPAD);
    float2 v[10];
    float mx = -1e30f;
#pragma unroll
    for (int i = 0; i < 10; i++) {
        int j = 2 * (lane + 32 * i);
        float2 t = p[lane + 32 * i];
        v[i].x = (j < Mk) ? t.x : -1e30f;
        v[i].y = (j + 1 < Mk) ? t.y : -1e30f;
        mx = fmaxf(mx, fmaxf(v[i].x, v[i].y));
    }
#pragma unroll
    for (int o = 16; o; o >>= 1) mx = fmaxf(mx, __shfl_xor_sync(0xffffffffu, mx, o));
    float sum = 0.f;
#pragma unroll
    for (int i = 0; i < 10; i++) {
        v[i].x = __expf(v[i].x - mx);
        v[i].y = __expf(v[i].y - mx);
        sum += v[i].x + v[i].y;
    }
#pragma unroll
    for (int o = 16; o; o >>= 1) sum += __shfl_xor_sync(0xffffffffu, sum, o);
    float r = SC_ATTN / sum;
    uint8_t* q = out + (size_t)row * MPAD;
#pragma unroll
    for (int i = 0; i < 10; i++) {
        int j = 2 * (lane + 32 * i);
        float o0 = (j < Mk) ? v[i].x * r : 0.f;
        float o1 = (j + 1 < Mk) ? v[i].y * r : 0.f;
        *(uint16_t*)(q + j) = pack_e4m3(o0, o1);
    }
}

// ---------------- host orchestration ----------------
static inline int ceil_div(int a, int b) { return (a + b - 1) / b; }

extern "C" void kernel_launch(void* const* d_in, const int* in_sizes, int n_in,
                              void* d_out, int out_size) {
    const float* x_in    = (const float*)d_in[0];
    const float* norm1_w = (const float*)d_in[1];
    const float* norm1_b = (const float*)d_in[2];
    const float* qkv_w   = (const float*)d_in[3];
    const float* qkv_b   = (const float*)d_in[4];
    const float* qn_w    = (const float*)d_in[5];
    const float* qn_b    = (const float*)d_in[6];
    const float* kn_w    = (const float*)d_in[7];
    const float* kn_b    = (const float*)d_in[8];
    const float* an_w    = (const float*)d_in[9];
    const float* an_b    = (const float*)d_in[10];
    const float* proj_w  = (const float*)d_in[11];
    const float* proj_b  = (const float*)d_in[12];
    const float* ls1     = (const float*)d_in[13];
    const float* norm2_w = (const float*)d_in[14];
    const float* norm2_b = (const float*)d_in[15];
    const float* fc1_w   = (const float*)d_in[16];
    const float* fc1_b   = (const float*)d_in[17];
    const float* fc2_w   = (const float*)d_in[18];
    const float* fc2_b   = (const float*)d_in[19];
    const float* ls2     = (const float*)d_in[20];
    float* out = (float*)d_out;

    cudaFuncSetAttribute(mma_gemm_nt, cudaFuncAttributeMaxDynamicSharedMemorySize, SMEM_DYN);

    float *px, *pq, *pk, *pscores, *phist;
    uint8_t *pmem, *pxn, *pq8, *pk8, *pvT, *pattn, *ppn, *ph;
    uint8_t *wqkv, *wproj, *wfc1, *wfc2;
    cudaGetSymbolAddress((void**)&px, g_x);
    cudaGetSymbolAddress((void**)&pq, g_q);
    cudaGetSymbolAddress((void**)&pk, g_k);
    cudaGetSymbolAddress((void**)&pscores, g_scores);
    cudaGetSymbolAddress((void**)&phist, g_hist);
    cudaGetSymbolAddress((void**)&pmem, g_mem8);
    cudaGetSymbolAddress((void**)&pxn, g_xn8);
    cudaGetSymbolAddress((void**)&pq8, g_q8);
    cudaGetSymbolAddress((void**)&pk8, g_k8);
    cudaGetSymbolAddress((void**)&pvT, g_vT8);
    cudaGetSymbolAddress((void**)&pattn, g_attn8);
    cudaGetSymbolAddress((void**)&ppn, g_pn8);
    cudaGetSymbolAddress((void**)&ph, g_h8);
    cudaGetSymbolAddress((void**)&wqkv, g_wqkv8);
    cudaGetSymbolAddress((void**)&wproj, g_wproj8);
    cudaGetSymbolAddress((void**)&wfc1, g_wfc18);
    cudaGetSymbolAddress((void**)&wfc2, g_wfc28);

    const float scale = 1.0f / sqrtf((float)DD);
    const int nXND = BB * NN * DD;
    const int rowsX = BB * NN;

    // epilogue alphas (undo operand scaling)
    const float aQK    = 1.0f / (SC_LN * SC_W);            // q,k gemms: 1/128
    const float aMEMW  = 1.0f / (SC_MEM * SC_W);           // k,v from mem: 1/128
    const float aSC    = scale / (SC_LN * SC_LN);          // scores
    const float aPV    = 1.0f / (SC_ATTN * SC_V);          // prod: 1/128
    const float aFC1   = 1.0f / (SC_LN * SC_W);            // 1/128
    const float aFC2   = 1.0f / (SC_H * SC_W);             // 1/512

    // weight conversions (fp32 -> e4m3 x32)
    {
        int n1 = LL * 3 * DD * DD / 2;
        cvt_w8_kernel<<<ceil_div(n1, 256), 256>>>(wqkv, qkv_w, n1);
        int n2 = LL * DD * DD / 2;
        cvt_w8_kernel<<<ceil_div(n2, 256), 256>>>(wproj, proj_w, n2);
        int n3 = LL * HH * DD / 2;
        cvt_w8_kernel<<<ceil_div(n3, 256), 256>>>(wfc1, fc1_w, n3);
        cvt_w8_kernel<<<ceil_div(n3, 256), 256>>>(wfc2, fc2_w, n3);
    }

    copy_kernel<<<ceil_div(nXND, 256), 256>>>(px, x_in, nXND);

    for (int r = 0; r < NRPT; r++) {
        int Mk = NN + r;
        int rowsM = BB * Mk;

        save_cls_kernel<<<ceil_div(BB * DD, 256), 256>>>(px, phist + (size_t)r * BB * DD);
        restore_patches_kernel<<<ceil_div(nXND, 256), 256>>>(px, x_in);
        build_mem8_kernel<<<ceil_div(BB * Mk * DD / 2, 256), 256>>>(pmem, px, phist, Mk);

        int mtX = ceil_div(rowsX, 128);
        int mtM = ceil_div(rowsM, 128);
        int ntMk = ceil_div(Mk, 128);

        for (int l = 0; l < LL; l++) {
            const uint8_t* Wq = wqkv + (size_t)l * 3 * DD * DD;
            const uint8_t* Wk = Wq + (size_t)DD * DD;
            const uint8_t* Wv = Wq + (size_t)2 * DD * DD;
            const float* bq = qkv_b + (size_t)l * 3 * DD;
            const float* bk = bq + DD;
            const float* bv = bq + 2 * DD;

            // norm1 -> xn (fp8 x4)
            ln_f8_kernel<<<ceil_div(rowsX, 8), 256>>>(px, pxn, norm1_w + l * DD, norm1_b + l * DD, rowsX);

            // q = xn @ Wq^T + bq  (f32)
            mma_gemm_nt<<<dim3(3, mtX, 1), 256, SMEM_DYN>>>(
                pxn, Wq, bq, 0, 0, pq, rowsX, DD, DD, DD, DD, DD, DD, 0, 0, 0, aQK, 1.f, 0);
            // k = mem @ Wk^T + bk (f32)
            mma_gemm_nt<<<dim3(3, mtM, 1), 256, SMEM_DYN>>>(
                pmem, Wk, bk, 0, 0, pk, rowsM, DD, DD, DD, DD, DD, DD, 0, 0, 0, aMEMW, 1.f, 0);
            // vT = Wv @ mem^T + bv(row) -> fp8 x8 [D, MPAD] per batch, pad zeros
            mma_gemm_nt<<<dim3(MPAD / 128, 3, BB), 256, SMEM_DYN>>>(
                Wv, pmem, bv, 0, 0, pvT, DD, Mk, MPAD, DD, DD, DD, MPAD,
                0, (long)Mk * DD, (long)DD * MPAD, aMEMW, SC_V, 3);

            // q/k layernorms -> fp8 x4
            ln_f8_kernel<<<ceil_div(rowsX, 8), 256>>>(pq, pq8, qn_w + l * DD, qn_b + l * DD, rowsX);
            ln_f8_kernel<<<ceil_div(rowsM, 8), 256>>>(pk, pk8, kn_w + l * DD, kn_b + l * DD, rowsM);

            // scores = scale * q @ k^T  (f32, per batch, ldc=MPAD)
            mma_gemm_nt<<<dim3(ntMk, ceil_div(NN, 128), BB), 256, SMEM_DYN>>>(
                pq8, pk8, 0, 0, 0, pscores, NN, Mk, Mk, DD, DD, DD, MPAD,
                (long)NN * DD, (long)Mk * DD, (long)NN * MPAD, aSC, 1.f, 0);
            softmax_f8_kernel<<<ceil_div(BB * NN, 8), 256>>>(pscores, pattn, BB * NN, Mk);

            // prod = attn @ vT^T  (f32, per batch; K = MPAD zero-padded)
            mma_gemm_nt<<<dim3(3, ceil_div(NN, 128), BB), 256, SMEM_DYN>>>(
                pattn, pvT, 0, 0, 0, pq, NN, DD, DD, MPAD, MPAD, MPAD, DD,
                (long)NN * MPAD, (long)DD * MPAD, (long)NN * DD, aPV, 1.f, 0);

            // attn-out layernorm -> fp8 x4
            ln_f8_kernel<<<ceil_div(rowsX, 8), 256>>>(pq, ppn, an_w + l * DD, an_b + l * DD, rowsX);

            // x += (prodn @ Wproj^T + bias) * ls1
            mma_gemm_nt<<<dim3(3, mtX, 1), 256, SMEM_DYN>>>(
                ppn, wproj + (size_t)l * DD * DD, proj_b + l * DD, ls1 + l * DD, px, px,
                rowsX, DD, DD, DD, DD, DD, DD, 0, 0, 0, aQK, 1.f, 2);

            // MLP
            ln_f8_kernel<<<ceil_div(rowsX, 8), 256>>>(px, pxn, norm2_w + l * DD, norm2_b + l * DD, rowsX);
            mma_gemm_nt<<<dim3(HH / 128, mtX, 1), 256, SMEM_DYN>>>(
                pxn, wfc1 + (size_t)l * HH * DD, fc1_b + l * HH, 0, 0, ph,
                rowsX, HH, HH, DD, DD, DD, HH, 0, 0, 0, aFC1, SC_H, 1);
            mma_gemm_nt<<<dim3(3, mtX, 1), 256, SMEM_DYN>>>(
                ph, wfc2 + (size_t)l * DD * HH, fc2_b + l * DD, ls2 + l * DD, px, px,
                rowsX, DD, DD, HH, HH, HH, DD, 0, 0, 0, aFC2, 1.f, 2);
        }
    }

    copy_kernel<<<ceil_div(nXND, 256), 256>>>(out, px, nXND);
}